// round 3
// baseline (speedup 1.0000x reference)
#include <cuda_runtime.h>

#define NMAX 256

// Scratch (allocation-free rule: __device__ globals)
__device__ float g_t224[(size_t)NMAX * 3 * 224 * 224]; // float t224 intermediate (NCHW)
__device__ float g_IM[NMAX * 6];                       // inverse affine per face

__constant__ float c_SRC[5][10] = {
    {103.284f,100.23f, 115.234f,99.98f, 71.48f,138.014f, 102.314f,178.1f,   114.05f,179.404f},
    {90.062f,100.236f, 131.136f,101.744f,79.354f,136.222f,90.354f,172.38f,  128.492f,173.516f},
    {79.46f,102.276f,  144.54f,102.276f, 112.0f,136.986f, 84.926f,174.02f,  139.074f,174.02f},
    {93.69f,101.744f,  134.764f,100.236f,145.474f,136.222f,96.334f,173.516f,134.472f,172.38f},
    {109.592f,99.98f,  121.542f,100.23f, 153.346f,138.014f,110.776f,179.404f,122.514f,178.1f}
};

// ---------------------------------------------------------------------------
// Kernel 1: Umeyama over 5 templates, argmin, invert, compose. One thread/face.
// ---------------------------------------------------------------------------
__global__ void est_kernel(const float* __restrict__ xs, float* __restrict__ out,
                           int N, long long off_imc, long long off_M)
{
    int n = blockIdx.x * blockDim.x + threadIdx.x;
    if (n >= N) return;

    float px[5], py[5];
#pragma unroll
    for (int i = 0; i < 5; i++) { px[i] = xs[n*10 + 2*i]; py[i] = xs[n*10 + 2*i + 1]; }

    float smx = 0.f, smy = 0.f;
#pragma unroll
    for (int i = 0; i < 5; i++) { smx += px[i]; smy += py[i]; }
    smx *= 0.2f; smy *= 0.2f;

    float sdx[5], sdy[5], var_sum = 0.f;
#pragma unroll
    for (int i = 0; i < 5; i++) {
        sdx[i] = px[i] - smx; sdy[i] = py[i] - smy;
        var_sum += sdx[i]*sdx[i] + sdy[i]*sdy[i];
    }
    var_sum *= 0.2f;

    float bestE = 3.4e38f;
    float bM[6] = {0,0,0,0,0,0};

#pragma unroll
    for (int k = 0; k < 5; k++) {
        const float* D = c_SRC[k];
        float dmx = 0.f, dmy = 0.f;
#pragma unroll
        for (int i = 0; i < 5; i++) { dmx += D[2*i]; dmy += D[2*i+1]; }
        dmx *= 0.2f; dmy *= 0.2f;

        // A[i][j] = sum_n dd[n,i]*sd[n,j] / 5
        float A00 = 0.f, A01 = 0.f, A10 = 0.f, A11 = 0.f;
#pragma unroll
        for (int i = 0; i < 5; i++) {
            float ddx = D[2*i]   - dmx;
            float ddy = D[2*i+1] - dmy;
            A00 += ddx * sdx[i]; A01 += ddx * sdy[i];
            A10 += ddy * sdx[i]; A11 += ddy * sdy[i];
        }
        A00 *= 0.2f; A01 *= 0.2f; A10 *= 0.2f; A11 *= 0.2f;

        float det = A00*A11 - A01*A10;
        float s   = (det > 0.f) ? 1.f : ((det < 0.f) ? -1.f : 0.f); // jnp.sign

        // Closed-form 2x2 SVD
        float E = (A00 + A11) * 0.5f;
        float F = (A00 - A11) * 0.5f;
        float G = (A10 + A01) * 0.5f;
        float H = (A10 - A01) * 0.5f;
        float Q  = hypotf(E, H);
        float Rr = hypotf(F, G);
        float sxv = Q + Rr;
        float syv = Q - Rr;
        float a1 = atan2f(G, F);
        float a2 = atan2f(H, E);
        float beta  = (a2 - a1) * 0.5f;
        float gamma = (a2 + a1) * 0.5f;
        float cg = cosf(gamma), sg = sinf(gamma);
        float cb = cosf(beta),  sb = sinf(beta);
        float sgn = (syv < 0.f) ? -1.f : 1.f;
        // Vt with row1 scaled by sgn
        float V00 = cb,        V01 = -sb;
        float V10 = sb * sgn,  V11 = cb * sgn;
        // R = U * diag(1, s) * Vt
        float R00 = cg * V00 - sg * s * V10;
        float R01 = cg * V01 - sg * s * V11;
        float R10 = sg * V00 + cg * s * V10;
        float R11 = sg * V01 + cg * s * V11;

        float scale = (sxv + fabsf(syv) * s) / var_sum;
        float tx = dmx - scale * (R00 * smx + R01 * smy);
        float ty = dmy - scale * (R10 * smx + R11 * smy);
        float M00 = scale * R00, M01 = scale * R01;
        float M10 = scale * R10, M11 = scale * R11;

        // residual: sum_i || M @ [p,1] - dst_i ||
        float e = 0.f;
#pragma unroll
        for (int i = 0; i < 5; i++) {
            float rx = M00*px[i] + M01*py[i] + tx - D[2*i];
            float ry = M10*px[i] + M11*py[i] + ty - D[2*i+1];
            e += sqrtf(rx*rx + ry*ry);
        }
        if (e < bestE) {
            bestE = e;
            bM[0] = M00; bM[1] = M01; bM[2] = tx;
            bM[3] = M10; bM[4] = M11; bM[5] = ty;
        }
    }

    // invert best M
    float det = bM[0]*bM[4] - bM[1]*bM[3];
    float ia  =  bM[4] / det;
    float ib  = -bM[1] / det;
    float ic  = -bM[3] / det;
    float idd =  bM[0] / det;
    float itx = -(ia * bM[2] + ib  * bM[5]);
    float ity = -(ic * bM[2] + idd * bM[5]);

    g_IM[n*6+0] = ia;  g_IM[n*6+1] = ib;  g_IM[n*6+2] = itx;
    g_IM[n*6+3] = ic;  g_IM[n*6+4] = idd; g_IM[n*6+5] = ity;

    // compose(IM, PREP_INV): reference computes _PREP_INV = invert(_PREP) in
    // float32; replicate that arithmetic exactly.
    float pa = 0.57142857f, pt = 32.f;
    float pdet = pa * pa;
    float pia  = pa / pdet;            // ~1.75
    float pitx = -(pia * pt);          // ~-56
    float C00 = ia  * pia,  C01 = ib  * pia;
    float C10 = ic  * pia,  C11 = idd * pia;
    float CT0 = ia * pitx + ib  * pitx + itx;
    float CT1 = ic * pitx + idd * pitx + ity;

    // outputs: xs copy, IM_composed, M
#pragma unroll
    for (int j = 0; j < 10; j++) out[n*10 + j] = xs[n*10 + j];
    float* oc = out + off_imc + (long long)n * 6;
    oc[0] = C00; oc[1] = C01; oc[2] = CT0; oc[3] = C10; oc[4] = C11; oc[5] = CT1;
    float* om = out + off_M + (long long)n * 6;
    om[0] = bM[0]; om[1] = bM[1]; om[2] = bM[2]; om[3] = bM[3]; om[4] = bM[4]; om[5] = bM[5];
}

// ---------------------------------------------------------------------------
// Kernel 2: warp img (1024x1024x3, HWC) -> t224 (NCHW float scratch) + u8 out
// ---------------------------------------------------------------------------
__global__ void warp224_kernel(const float* __restrict__ img, float* __restrict__ out,
                               int N, long long off_u8)
{
    int total = N * 224 * 224;
    for (int idx = blockIdx.x * blockDim.x + threadIdx.x; idx < total;
         idx += gridDim.x * blockDim.x) {
        int x = idx % 224;
        int y = (idx / 224) % 224;
        int n = idx / (224 * 224);

        float i0 = g_IM[n*6+0], i1 = g_IM[n*6+1], i2 = g_IM[n*6+2];
        float i3 = g_IM[n*6+3], i4 = g_IM[n*6+4], i5 = g_IM[n*6+5];
        float gx = (float)x, gy = (float)y;
        float sx = i0 * gx + i1 * gy + i2;
        float sy = i3 * gx + i4 * gy + i5;

        float x0f = floorf(sx), y0f = floorf(sy);
        float fx = sx - x0f,    fy = sy - y0f;
        int x0 = (int)x0f, y0 = (int)y0f;
        int x1 = x0 + 1,   y1 = y0 + 1;
        const int W = 1024, H = 1024;
        float vx0 = (x0 >= 0 && x0 < W) ? 1.f : 0.f;
        float vx1 = (x1 >= 0 && x1 < W) ? 1.f : 0.f;
        float vy0 = (y0 >= 0 && y0 < H) ? 1.f : 0.f;
        float vy1 = (y1 >= 0 && y1 < H) ? 1.f : 0.f;
        float w00 = (1.f - fx) * (1.f - fy) * vx0 * vy0;
        float w10 = fx         * (1.f - fy) * vx1 * vy0;
        float w01 = (1.f - fx) * fy         * vx0 * vy1;
        float w11 = fx         * fy         * vx1 * vy1;
        int x0c = min(max(x0, 0), W-1), x1c = min(max(x1, 0), W-1);
        int y0c = min(max(y0, 0), H-1), y1c = min(max(y1, 0), H-1);

        const float* p00 = img + ((long long)y0c * W + x0c) * 3;
        const float* p10 = img + ((long long)y0c * W + x1c) * 3;
        const float* p01 = img + ((long long)y1c * W + x0c) * 3;
        const float* p11 = img + ((long long)y1c * W + x1c) * 3;

        float r = __ldg(p00+0)*w00 + __ldg(p10+0)*w10 + __ldg(p01+0)*w01 + __ldg(p11+0)*w11;
        float g = __ldg(p00+1)*w00 + __ldg(p10+1)*w10 + __ldg(p01+1)*w01 + __ldg(p11+1)*w11;
        float b = __ldg(p00+2)*w00 + __ldg(p10+2)*w10 + __ldg(p01+2)*w01 + __ldg(p11+2)*w11;

        const int plane = 224 * 224;
        long long base = ((long long)n * 3) * plane + (long long)y * 224 + x;
        g_t224[base]             = r;
        g_t224[base +     plane] = g;
        g_t224[base + 2 * plane] = b;

        float* ou = out + off_u8 + ((long long)idx) * 3;
        ou[0] = (float)(unsigned char)r;
        ou[1] = (float)(unsigned char)g;
        ou[2] = (float)(unsigned char)b;
    }
}

// ---------------------------------------------------------------------------
// Kernel 3: warp t224 (float scratch) -> t192 out (NCHW), fixed 1.75x zoom
// ---------------------------------------------------------------------------
__global__ void warp192_kernel(float* __restrict__ out, int N, long long off_t192)
{
    int total = N * 192 * 192;
    for (int idx = blockIdx.x * blockDim.x + threadIdx.x; idx < total;
         idx += gridDim.x * blockDim.x) {
        int x = idx % 192;
        int y = (idx / 192) % 192;
        int n = idx / (192 * 192);

        // invert(_PREP) in float32, matching reference
        float pa = 0.57142857f, pt = 32.f;
        float pdet = pa * pa;
        float pia  = pa / pdet;
        float pitx = -(pia * pt);

        float sx = pia * (float)x + pitx;
        float sy = pia * (float)y + pitx;

        float x0f = floorf(sx), y0f = floorf(sy);
        float fx = sx - x0f,    fy = sy - y0f;
        int x0 = (int)x0f, y0 = (int)y0f;
        int x1 = x0 + 1,   y1 = y0 + 1;
        const int W = 224, H = 224;
        float vx0 = (x0 >= 0 && x0 < W) ? 1.f : 0.f;
        float vx1 = (x1 >= 0 && x1 < W) ? 1.f : 0.f;
        float vy0 = (y0 >= 0 && y0 < H) ? 1.f : 0.f;
        float vy1 = (y1 >= 0 && y1 < H) ? 1.f : 0.f;
        float w00 = (1.f - fx) * (1.f - fy) * vx0 * vy0;
        float w10 = fx         * (1.f - fy) * vx1 * vy0;
        float w01 = (1.f - fx) * fy         * vx0 * vy1;
        float w11 = fx         * fy         * vx1 * vy1;
        int x0c = min(max(x0, 0), W-1), x1c = min(max(x1, 0), W-1);
        int y0c = min(max(y0, 0), H-1), y1c = min(max(y1, 0), H-1);

        const int plane = 224 * 224;
        long long pbase = (long long)n * 3 * plane;

#pragma unroll
        for (int c = 0; c < 3; c++) {
            const float* pl = g_t224 + pbase + (long long)c * plane;
            float acc = pl[y0c * W + x0c] * w00
                      + pl[y0c * W + x1c] * w10
                      + pl[y1c * W + x0c] * w01
                      + pl[y1c * W + x1c] * w11;
            out[off_t192 + ((long long)(n * 3 + c) * 192 + y) * 192 + x] = acc;
        }
    }
}

// ---------------------------------------------------------------------------
extern "C" void kernel_launch(void* const* d_in, const int* in_sizes, int n_in,
                              void* d_out, int out_size)
{
    const float* xs  = (const float*)d_in[0];
    const float* img = (const float*)d_in[1];
    float* out = (float*)d_out;

    int N = in_sizes[0] / 10;   // (N,5,2)
    if (N > NMAX) N = NMAX;

    // output layout (float32): xs | IM_composed | imgs_u8 | t192 | M
    long long off_imc  = 10LL * N;
    long long off_u8   = off_imc + 6LL * N;
    long long off_t192 = off_u8 + 150528LL * N;   // 224*224*3
    long long off_M    = off_t192 + 110592LL * N; // 192*192*3

    est_kernel<<<(N + 127) / 128, 128>>>(xs, out, N, off_imc, off_M);

    int t224_total = N * 224 * 224;
    int g224 = (t224_total + 255) / 256; if (g224 > 148 * 32) g224 = 148 * 32;
    warp224_kernel<<<g224, 256>>>(img, out, N, off_u8);

    int t192_total = N * 192 * 192;
    int g192 = (t192_total + 255) / 256; if (g192 > 148 * 32) g192 = 148 * 32;
    warp192_kernel<<<g192, 256>>>(out, N, off_t192);
}

// round 4
// speedup vs baseline: 1.3694x; 1.3694x over previous
#include <cuda_runtime.h>

#define NMAX 256

// Scratch (allocation-free rule: __device__ globals)
__device__ float4 g_img4[1024 * 1024];   // repacked source image (RGBA, pad=0)
__device__ float  g_IM[NMAX * 6];        // inverse affine per face

__constant__ float c_SRC[5][10] = {
    {103.284f,100.23f, 115.234f,99.98f, 71.48f,138.014f, 102.314f,178.1f,   114.05f,179.404f},
    {90.062f,100.236f, 131.136f,101.744f,79.354f,136.222f,90.354f,172.38f,  128.492f,173.516f},
    {79.46f,102.276f,  144.54f,102.276f, 112.0f,136.986f, 84.926f,174.02f,  139.074f,174.02f},
    {93.69f,101.744f,  134.764f,100.236f,145.474f,136.222f,96.334f,173.516f,134.472f,172.38f},
    {109.592f,99.98f,  121.542f,100.23f, 153.346f,138.014f,110.776f,179.404f,122.514f,178.1f}
};

// ---------------------------------------------------------------------------
// Kernel 1: Umeyama over 5 templates, argmin, invert, compose. One thread/face.
// ---------------------------------------------------------------------------
__global__ void est_kernel(const float* __restrict__ xs, float* __restrict__ out,
                           int N, long long off_imc, long long off_M)
{
    int n = blockIdx.x * blockDim.x + threadIdx.x;
    if (n >= N) return;

    float px[5], py[5];
#pragma unroll
    for (int i = 0; i < 5; i++) { px[i] = xs[n*10 + 2*i]; py[i] = xs[n*10 + 2*i + 1]; }

    float smx = 0.f, smy = 0.f;
#pragma unroll
    for (int i = 0; i < 5; i++) { smx += px[i]; smy += py[i]; }
    smx *= 0.2f; smy *= 0.2f;

    float sdx[5], sdy[5], var_sum = 0.f;
#pragma unroll
    for (int i = 0; i < 5; i++) {
        sdx[i] = px[i] - smx; sdy[i] = py[i] - smy;
        var_sum += sdx[i]*sdx[i] + sdy[i]*sdy[i];
    }
    var_sum *= 0.2f;

    float bestE = 3.4e38f;
    float bM[6] = {0,0,0,0,0,0};

#pragma unroll
    for (int k = 0; k < 5; k++) {
        const float* D = c_SRC[k];
        float dmx = 0.f, dmy = 0.f;
#pragma unroll
        for (int i = 0; i < 5; i++) { dmx += D[2*i]; dmy += D[2*i+1]; }
        dmx *= 0.2f; dmy *= 0.2f;

        float A00 = 0.f, A01 = 0.f, A10 = 0.f, A11 = 0.f;
#pragma unroll
        for (int i = 0; i < 5; i++) {
            float ddx = D[2*i]   - dmx;
            float ddy = D[2*i+1] - dmy;
            A00 += ddx * sdx[i]; A01 += ddx * sdy[i];
            A10 += ddy * sdx[i]; A11 += ddy * sdy[i];
        }
        A00 *= 0.2f; A01 *= 0.2f; A10 *= 0.2f; A11 *= 0.2f;

        float det = A00*A11 - A01*A10;
        float s   = (det > 0.f) ? 1.f : ((det < 0.f) ? -1.f : 0.f);

        float E = (A00 + A11) * 0.5f;
        float F = (A00 - A11) * 0.5f;
        float G = (A10 + A01) * 0.5f;
        float H = (A10 - A01) * 0.5f;
        float Q  = hypotf(E, H);
        float Rr = hypotf(F, G);
        float sxv = Q + Rr;
        float syv = Q - Rr;
        float a1 = atan2f(G, F);
        float a2 = atan2f(H, E);
        float beta  = (a2 - a1) * 0.5f;
        float gamma = (a2 + a1) * 0.5f;
        float cg = cosf(gamma), sg = sinf(gamma);
        float cb = cosf(beta),  sb = sinf(beta);
        float sgn = (syv < 0.f) ? -1.f : 1.f;
        float V00 = cb,        V01 = -sb;
        float V10 = sb * sgn,  V11 = cb * sgn;
        float R00 = cg * V00 - sg * s * V10;
        float R01 = cg * V01 - sg * s * V11;
        float R10 = sg * V00 + cg * s * V10;
        float R11 = sg * V01 + cg * s * V11;

        float scale = (sxv + fabsf(syv) * s) / var_sum;
        float tx = dmx - scale * (R00 * smx + R01 * smy);
        float ty = dmy - scale * (R10 * smx + R11 * smy);
        float M00 = scale * R00, M01 = scale * R01;
        float M10 = scale * R10, M11 = scale * R11;

        float e = 0.f;
#pragma unroll
        for (int i = 0; i < 5; i++) {
            float rx = M00*px[i] + M01*py[i] + tx - D[2*i];
            float ry = M10*px[i] + M11*py[i] + ty - D[2*i+1];
            e += sqrtf(rx*rx + ry*ry);
        }
        if (e < bestE) {
            bestE = e;
            bM[0] = M00; bM[1] = M01; bM[2] = tx;
            bM[3] = M10; bM[4] = M11; bM[5] = ty;
        }
    }

    float det = bM[0]*bM[4] - bM[1]*bM[3];
    float ia  =  bM[4] / det;
    float ib  = -bM[1] / det;
    float ic  = -bM[3] / det;
    float idd =  bM[0] / det;
    float itx = -(ia * bM[2] + ib  * bM[5]);
    float ity = -(ic * bM[2] + idd * bM[5]);

    g_IM[n*6+0] = ia;  g_IM[n*6+1] = ib;  g_IM[n*6+2] = itx;
    g_IM[n*6+3] = ic;  g_IM[n*6+4] = idd; g_IM[n*6+5] = ity;

    float pa = 0.57142857f, pt = 32.f;
    float pdet = pa * pa;
    float pia  = pa / pdet;
    float pitx = -(pia * pt);
    float C00 = ia  * pia,  C01 = ib  * pia;
    float C10 = ic  * pia,  C11 = idd * pia;
    float CT0 = ia * pitx + ib  * pitx + itx;
    float CT1 = ic * pitx + idd * pitx + ity;

#pragma unroll
    for (int j = 0; j < 10; j++) out[n*10 + j] = xs[n*10 + j];
    float* oc = out + off_imc + (long long)n * 6;
    oc[0] = C00; oc[1] = C01; oc[2] = CT0; oc[3] = C10; oc[4] = C11; oc[5] = CT1;
    float* om = out + off_M + (long long)n * 6;
    om[0] = bM[0]; om[1] = bM[1]; om[2] = bM[2]; om[3] = bM[3]; om[4] = bM[4]; om[5] = bM[5];
}

// ---------------------------------------------------------------------------
// Kernel 2: repack HWC float3 image -> float4 (aligned 16B taps)
// ---------------------------------------------------------------------------
__global__ void img4_kernel(const float* __restrict__ img)
{
    int i = blockIdx.x * blockDim.x + threadIdx.x;
    if (i < 1024 * 1024) {
        g_img4[i] = make_float4(img[3*i], img[3*i+1], img[3*i+2], 0.f);
    }
}

// ---------------------------------------------------------------------------
// Kernel 3 (fused): per (face, 8-row tile):
//   phase 1: bilinear-warp img -> 9-row t224 tile in smem (+u8 output, 8 rows)
//   phase 2: 1.75x-zoom bilinear t224-tile -> t192 rows owned by this tile
// ---------------------------------------------------------------------------
__global__ __launch_bounds__(256) void fused_warp_kernel(float* __restrict__ out,
                                                         long long off_u8,
                                                         long long off_t192)
{
    __shared__ float sm[3][9][224];   // 24192 B tile (halo row included)
    __shared__ float sIM[6];

    int blk  = blockIdx.x;
    int tile = blk % 28;
    int n    = blk / 28;
    int r0   = tile * 8;
    int tid  = threadIdx.x;

    if (tid < 6) sIM[tid] = g_IM[n*6 + tid];
    __syncthreads();
    float i0 = sIM[0], i1 = sIM[1], i2 = sIM[2];
    float i3 = sIM[3], i4 = sIM[4], i5 = sIM[5];

    // ---- phase 1: fill t224 tile (rows r0 .. r0+8, clip at 223) ----
    int rows  = (r0 + 8 < 224) ? 9 : 8;
    int items = rows * 224;
    for (int px = tid; px < items; px += 256) {
        int ry = px / 224;
        int x  = px - ry * 224;
        int y  = r0 + ry;

        float gx = (float)x, gy = (float)y;
        float sx = i0 * gx + i1 * gy + i2;
        float sy = i3 * gx + i4 * gy + i5;

        float x0f = floorf(sx), y0f = floorf(sy);
        float fx = sx - x0f,    fy = sy - y0f;
        int x0 = (int)x0f, y0 = (int)y0f;
        int x1 = x0 + 1,   y1 = y0 + 1;
        const int W = 1024, H = 1024;
        float vx0 = (x0 >= 0 && x0 < W) ? 1.f : 0.f;
        float vx1 = (x1 >= 0 && x1 < W) ? 1.f : 0.f;
        float vy0 = (y0 >= 0 && y0 < H) ? 1.f : 0.f;
        float vy1 = (y1 >= 0 && y1 < H) ? 1.f : 0.f;
        float w00 = (1.f - fx) * (1.f - fy) * vx0 * vy0;
        float w10 = fx         * (1.f - fy) * vx1 * vy0;
        float w01 = (1.f - fx) * fy         * vx0 * vy1;
        float w11 = fx         * fy         * vx1 * vy1;
        int x0c = min(max(x0, 0), W-1), x1c = min(max(x1, 0), W-1);
        int y0c = min(max(y0, 0), H-1), y1c = min(max(y1, 0), H-1);

        float4 v00 = g_img4[y0c * W + x0c];
        float4 v10 = g_img4[y0c * W + x1c];
        float4 v01 = g_img4[y1c * W + x0c];
        float4 v11 = g_img4[y1c * W + x1c];

        float r = v00.x*w00 + v10.x*w10 + v01.x*w01 + v11.x*w11;
        float g = v00.y*w00 + v10.y*w10 + v01.y*w01 + v11.y*w11;
        float b = v00.z*w00 + v10.z*w10 + v01.z*w01 + v11.z*w11;

        sm[0][ry][x] = r;
        sm[1][ry][x] = g;
        sm[2][ry][x] = b;

        if (ry < 8) {
            float* ou = out + off_u8 + ((long long)((n * 224 + y) * 224 + x)) * 3;
            ou[0] = (float)(unsigned char)r;
            ou[1] = (float)(unsigned char)g;
            ou[2] = (float)(unsigned char)b;
        }
    }
    __syncthreads();

    // ---- phase 2: t192 rows whose y0 taps live in this tile ----
    float pa = 0.57142857f, pt = 32.f;
    float pdet = pa * pa;
    float pia  = pa / pdet;      // matches reference float arithmetic
    float pitx = -(pia * pt);

    for (int y = 0; y < 192; y++) {
        float syf = pia * (float)y + pitx;
        float y0f = floorf(syf);
        int y0 = (int)y0f;
        // exact partition: tile 0 absorbs y0<0, tile 27 absorbs y0>=224
        bool lo = (y0 >= r0) || (r0 == 0   && y0 < 0);
        bool hi = (y0 < r0+8) || (r0 == 216 && y0 >= 224);
        if (!(lo && hi)) continue;

        float fy = syf - y0f;
        int y1 = y0 + 1;
        float vy0 = (y0 >= 0 && y0 < 224) ? 1.f : 0.f;
        float vy1 = (y1 >= 0 && y1 < 224) ? 1.f : 0.f;
        int y0c = min(max(y0, 0), 223);
        int y1c = min(max(y1, 0), 223);
        int ry0 = min(max(y0c - r0, 0), 8);
        int ry1 = min(max(y1c - r0, 0), 8);

        for (int x = tid; x < 192; x += 256) {
            float sxf = pia * (float)x + pitx;
            float x0f = floorf(sxf);
            int x0 = (int)x0f;
            float fx = sxf - x0f;
            int x1 = x0 + 1;
            float vx0 = (x0 >= 0 && x0 < 224) ? 1.f : 0.f;
            float vx1 = (x1 >= 0 && x1 < 224) ? 1.f : 0.f;
            float w00 = (1.f - fx) * (1.f - fy) * vx0 * vy0;
            float w10 = fx         * (1.f - fy) * vx1 * vy0;
            float w01 = (1.f - fx) * fy         * vx0 * vy1;
            float w11 = fx         * fy         * vx1 * vy1;
            int x0c = min(max(x0, 0), 223);
            int x1c = min(max(x1, 0), 223);

#pragma unroll
            for (int c = 0; c < 3; c++) {
                float acc = sm[c][ry0][x0c] * w00
                          + sm[c][ry0][x1c] * w10
                          + sm[c][ry1][x0c] * w01
                          + sm[c][ry1][x1c] * w11;
                out[off_t192 + ((long long)(n * 3 + c) * 192 + y) * 192 + x] = acc;
            }
        }
    }
}

// ---------------------------------------------------------------------------
extern "C" void kernel_launch(void* const* d_in, const int* in_sizes, int n_in,
                              void* d_out, int out_size)
{
    const float* xs  = (const float*)d_in[0];
    const float* img = (const float*)d_in[1];
    float* out = (float*)d_out;

    int N = in_sizes[0] / 10;   // (N,5,2)
    if (N > NMAX) N = NMAX;

    // output layout (float32): xs | IM_composed | imgs_u8 | t192 | M
    long long off_imc  = 10LL * N;
    long long off_u8   = off_imc + 6LL * N;
    long long off_t192 = off_u8 + 150528LL * N;   // 224*224*3
    long long off_M    = off_t192 + 110592LL * N; // 192*192*3

    est_kernel<<<(N + 127) / 128, 128>>>(xs, out, N, off_imc, off_M);

    img4_kernel<<<(1024 * 1024 + 255) / 256, 256>>>(img);

    fused_warp_kernel<<<28 * N, 256>>>(out, off_u8, off_t192);
}

// round 6
// speedup vs baseline: 2.6633x; 1.9449x over previous
#include <cuda_runtime.h>

#define NMAX 256

// Scratch (allocation-free rule: __device__ globals)
__device__ float4 g_img4[1024 * 1024];   // repacked source image (RGBA, pad=0)
__device__ float  g_IM[NMAX * 6];        // inverse affine per face
__device__ int2   g_rowrange[28];        // t192 rows owned by each 8-row tile

__constant__ float c_SRC[5][10] = {
    {103.284f,100.23f, 115.234f,99.98f, 71.48f,138.014f, 102.314f,178.1f,   114.05f,179.404f},
    {90.062f,100.236f, 131.136f,101.744f,79.354f,136.222f,90.354f,172.38f,  128.492f,173.516f},
    {79.46f,102.276f,  144.54f,102.276f, 112.0f,136.986f, 84.926f,174.02f,  139.074f,174.02f},
    {93.69f,101.744f,  134.764f,100.236f,145.474f,136.222f,96.334f,173.516f,134.472f,172.38f},
    {109.592f,99.98f,  121.542f,100.23f, 153.346f,138.014f,110.776f,179.404f,122.514f,178.1f}
};

// ---------------------------------------------------------------------------
// est: Umeyama over 5 templates, argmin, invert, compose. One thread/face.
// ---------------------------------------------------------------------------
__device__ void est_face(const float* __restrict__ xs, float* __restrict__ out,
                         int n, long long off_imc, long long off_M)
{
    float px[5], py[5];
#pragma unroll
    for (int i = 0; i < 5; i++) { px[i] = xs[n*10 + 2*i]; py[i] = xs[n*10 + 2*i + 1]; }

    float smx = 0.f, smy = 0.f;
#pragma unroll
    for (int i = 0; i < 5; i++) { smx += px[i]; smy += py[i]; }
    smx *= 0.2f; smy *= 0.2f;

    float sdx[5], sdy[5], var_sum = 0.f;
#pragma unroll
    for (int i = 0; i < 5; i++) {
        sdx[i] = px[i] - smx; sdy[i] = py[i] - smy;
        var_sum += sdx[i]*sdx[i] + sdy[i]*sdy[i];
    }
    var_sum *= 0.2f;

    float bestE = 3.4e38f;
    float bM[6] = {0,0,0,0,0,0};

#pragma unroll
    for (int k = 0; k < 5; k++) {
        const float* D = c_SRC[k];
        float dmx = 0.f, dmy = 0.f;
#pragma unroll
        for (int i = 0; i < 5; i++) { dmx += D[2*i]; dmy += D[2*i+1]; }
        dmx *= 0.2f; dmy *= 0.2f;

        float A00 = 0.f, A01 = 0.f, A10 = 0.f, A11 = 0.f;
#pragma unroll
        for (int i = 0; i < 5; i++) {
            float ddx = D[2*i]   - dmx;
            float ddy = D[2*i+1] - dmy;
            A00 += ddx * sdx[i]; A01 += ddx * sdy[i];
            A10 += ddy * sdx[i]; A11 += ddy * sdy[i];
        }
        A00 *= 0.2f; A01 *= 0.2f; A10 *= 0.2f; A11 *= 0.2f;

        float det = A00*A11 - A01*A10;
        float s   = (det > 0.f) ? 1.f : ((det < 0.f) ? -1.f : 0.f);

        float E = (A00 + A11) * 0.5f;
        float F = (A00 - A11) * 0.5f;
        float G = (A10 + A01) * 0.5f;
        float H = (A10 - A01) * 0.5f;
        float Q  = hypotf(E, H);
        float Rr = hypotf(F, G);
        float sxv = Q + Rr;
        float syv = Q - Rr;
        float a1 = atan2f(G, F);
        float a2 = atan2f(H, E);
        float beta  = (a2 - a1) * 0.5f;
        float gamma = (a2 + a1) * 0.5f;
        float cg = cosf(gamma), sg = sinf(gamma);
        float cb = cosf(beta),  sb = sinf(beta);
        float sgn = (syv < 0.f) ? -1.f : 1.f;
        float V00 = cb,        V01 = -sb;
        float V10 = sb * sgn,  V11 = cb * sgn;
        float R00 = cg * V00 - sg * s * V10;
        float R01 = cg * V01 - sg * s * V11;
        float R10 = sg * V00 + cg * s * V10;
        float R11 = sg * V01 + cg * s * V11;

        float scale = (sxv + fabsf(syv) * s) / var_sum;
        float tx = dmx - scale * (R00 * smx + R01 * smy);
        float ty = dmy - scale * (R10 * smx + R11 * smy);
        float M00 = scale * R00, M01 = scale * R01;
        float M10 = scale * R10, M11 = scale * R11;

        float e = 0.f;
#pragma unroll
        for (int i = 0; i < 5; i++) {
            float rx = M00*px[i] + M01*py[i] + tx - D[2*i];
            float ry = M10*px[i] + M11*py[i] + ty - D[2*i+1];
            e += sqrtf(rx*rx + ry*ry);
        }
        if (e < bestE) {
            bestE = e;
            bM[0] = M00; bM[1] = M01; bM[2] = tx;
            bM[3] = M10; bM[4] = M11; bM[5] = ty;
        }
    }

    float det = bM[0]*bM[4] - bM[1]*bM[3];
    float ia  =  bM[4] / det;
    float ib  = -bM[1] / det;
    float ic  = -bM[3] / det;
    float idd =  bM[0] / det;
    float itx = -(ia * bM[2] + ib  * bM[5]);
    float ity = -(ic * bM[2] + idd * bM[5]);

    g_IM[n*6+0] = ia;  g_IM[n*6+1] = ib;  g_IM[n*6+2] = itx;
    g_IM[n*6+3] = ic;  g_IM[n*6+4] = idd; g_IM[n*6+5] = ity;

    float pa = 0.57142857f, pt = 32.f;
    float pdet = pa * pa;
    float pia  = pa / pdet;
    float pitx = -(pia * pt);
    float C00 = ia  * pia,  C01 = ib  * pia;
    float C10 = ic  * pia,  C11 = idd * pia;
    float CT0 = ia * pitx + ib  * pitx + itx;
    float CT1 = ic * pitx + idd * pitx + ity;

#pragma unroll
    for (int j = 0; j < 10; j++) out[n*10 + j] = xs[n*10 + j];
    float* oc = out + off_imc + (long long)n * 6;
    oc[0] = C00; oc[1] = C01; oc[2] = CT0; oc[3] = C10; oc[4] = C11; oc[5] = CT1;
    float* om = out + off_M + (long long)n * 6;
    om[0] = bM[0]; om[1] = bM[1]; om[2] = bM[2]; om[3] = bM[3]; om[4] = bM[4]; om[5] = bM[5];
}

// ---------------------------------------------------------------------------
// Kernel A (prep): blocks [0,1024): img repack (4px/thread, float4 IO)
//                  block 1024: est for all faces
//                  block 1025: t192 tile row-ranges
// ---------------------------------------------------------------------------
__global__ __launch_bounds__(256) void prep_kernel(const float* __restrict__ img,
                                                   const float* __restrict__ xs,
                                                   float* __restrict__ out,
                                                   int N, long long off_imc, long long off_M)
{
    int blk = blockIdx.x;
    int tid = threadIdx.x;

    if (blk < 1024) {
        int j = blk * 256 + tid;            // 4-pixel group id, j < 262144
        const float4* im4 = (const float4*)img;
        float4 a = im4[3*j+0];
        float4 b = im4[3*j+1];
        float4 c = im4[3*j+2];
        g_img4[4*j+0] = make_float4(a.x, a.y, a.z, 0.f);
        g_img4[4*j+1] = make_float4(a.w, b.x, b.y, 0.f);
        g_img4[4*j+2] = make_float4(b.z, b.w, c.x, 0.f);
        g_img4[4*j+3] = make_float4(c.y, c.z, c.w, 0.f);
    } else if (blk == 1024) {
        if (tid < N) est_face(xs, out, tid, off_imc, off_M);
    } else {
        __shared__ int s_lo[28], s_hi[28];
        if (tid < 28) { s_lo[tid] = 192; s_hi[tid] = -1; }
        __syncthreads();
        if (tid < 192) {
            float pa = 0.57142857f, pt = 32.f;
            float pdet = pa * pa;
            float pia  = pa / pdet;
            float pitx = -(pia * pt);
            float syf = pia * (float)tid + pitx;
            int y0 = (int)floorf(syf);
            int t = (y0 < 0) ? 0 : ((y0 >= 224) ? 27 : (y0 >> 3));
            atomicMin(&s_lo[t], tid);
            atomicMax(&s_hi[t], tid);
        }
        __syncthreads();
        if (tid < 28) g_rowrange[tid] = make_int2(s_lo[tid], s_hi[tid]);
    }
}

// ---------------------------------------------------------------------------
// Kernel B (fused): per (face, 8-row tile):
//   phase 1: bilinear-warp img -> 9-row t224 tile in smem (+u8 output, 8 rows)
//   phase 2: 1.75x-zoom bilinear tile -> owned t192 rows
// ---------------------------------------------------------------------------
__global__ __launch_bounds__(256) void fused_warp_kernel(float* __restrict__ out,
                                                         long long off_u8,
                                                         long long off_t192)
{
    __shared__ float sm[3][9][224];   // 24192 B tile (halo row included)
    __shared__ float sIM[6];
    __shared__ int   sRange[2];

    int blk  = blockIdx.x;
    int tile = blk % 28;
    int n    = blk / 28;
    int r0   = tile * 8;
    int tid  = threadIdx.x;

    if (tid < 6) sIM[tid] = g_IM[n*6 + tid];
    if (tid == 6) { int2 rr = g_rowrange[tile]; sRange[0] = rr.x; sRange[1] = rr.y; }
    __syncthreads();
    float i0 = sIM[0], i1 = sIM[1], i2 = sIM[2];
    float i3 = sIM[3], i4 = sIM[4], i5 = sIM[5];

    // ---- phase 1: fill t224 tile, 4 px per thread-item ----
    int rows   = (r0 + 8 < 224) ? 9 : 8;
    int items4 = rows * 56;                      // 56 groups of 4 px per row
    for (int it = tid; it < items4; it += 256) {
        int ry = it / 56;
        int xq = (it - ry * 56) * 4;
        int y  = r0 + ry;
        float gy = (float)y;

        float sxv[4], syv[4];
#pragma unroll
        for (int j = 0; j < 4; j++) {
            float gx = (float)(xq + j);
            sxv[j] = i0 * gx + i1 * gy + i2;
            syv[j] = i3 * gx + i4 * gy + i5;
        }

        float rr[4], gg[4], bb[4];
        bool interior = (sxv[0] >= 0.f) & (sxv[0] < 1023.f) &
                        (sxv[3] >= 0.f) & (sxv[3] < 1023.f) &
                        (syv[0] >= 0.f) & (syv[0] < 1023.f) &
                        (syv[3] >= 0.f) & (syv[3] < 1023.f);
        if (interior) {
#pragma unroll
            for (int j = 0; j < 4; j++) {
                float x0f = floorf(sxv[j]), y0f = floorf(syv[j]);
                float fx = sxv[j] - x0f,    fy = syv[j] - y0f;
                int x0 = (int)x0f, y0 = (int)y0f;
                float w00 = (1.f - fx) * (1.f - fy);
                float w10 = fx         * (1.f - fy);
                float w01 = (1.f - fx) * fy;
                float w11 = fx         * fy;
                int base0 = y0 * 1024 + x0;
                float4 v00 = g_img4[base0];
                float4 v10 = g_img4[base0 + 1];
                float4 v01 = g_img4[base0 + 1024];
                float4 v11 = g_img4[base0 + 1025];
                rr[j] = v00.x*w00 + v10.x*w10 + v01.x*w01 + v11.x*w11;
                gg[j] = v00.y*w00 + v10.y*w10 + v01.y*w01 + v11.y*w11;
                bb[j] = v00.z*w00 + v10.z*w10 + v01.z*w01 + v11.z*w11;
            }
        } else {
#pragma unroll
            for (int j = 0; j < 4; j++) {
                float x0f = floorf(sxv[j]), y0f = floorf(syv[j]);
                float fx = sxv[j] - x0f,    fy = syv[j] - y0f;
                int x0 = (int)x0f, y0 = (int)y0f;
                int x1 = x0 + 1,   y1 = y0 + 1;
                const int W = 1024, H = 1024;
                float vx0 = (x0 >= 0 && x0 < W) ? 1.f : 0.f;
                float vx1 = (x1 >= 0 && x1 < W) ? 1.f : 0.f;
                float vy0 = (y0 >= 0 && y0 < H) ? 1.f : 0.f;
                float vy1 = (y1 >= 0 && y1 < H) ? 1.f : 0.f;
                float w00 = (1.f - fx) * (1.f - fy) * vx0 * vy0;
                float w10 = fx         * (1.f - fy) * vx1 * vy0;
                float w01 = (1.f - fx) * fy         * vx0 * vy1;
                float w11 = fx         * fy         * vx1 * vy1;
                int x0c = min(max(x0, 0), W-1), x1c = min(max(x1, 0), W-1);
                int y0c = min(max(y0, 0), H-1), y1c = min(max(y1, 0), H-1);
                float4 v00 = g_img4[y0c * W + x0c];
                float4 v10 = g_img4[y0c * W + x1c];
                float4 v01 = g_img4[y1c * W + x0c];
                float4 v11 = g_img4[y1c * W + x1c];
                rr[j] = v00.x*w00 + v10.x*w10 + v01.x*w01 + v11.x*w11;
                gg[j] = v00.y*w00 + v10.y*w10 + v01.y*w01 + v11.y*w11;
                bb[j] = v00.z*w00 + v10.z*w10 + v01.z*w01 + v11.z*w11;
            }
        }

        *(float4*)&sm[0][ry][xq] = make_float4(rr[0], rr[1], rr[2], rr[3]);
        *(float4*)&sm[1][ry][xq] = make_float4(gg[0], gg[1], gg[2], gg[3]);
        *(float4*)&sm[2][ry][xq] = make_float4(bb[0], bb[1], bb[2], bb[3]);

        if (ry < 8) {
            float u[12];
#pragma unroll
            for (int j = 0; j < 4; j++) {
                u[3*j+0] = (float)(unsigned char)rr[j];
                u[3*j+1] = (float)(unsigned char)gg[j];
                u[3*j+2] = (float)(unsigned char)bb[j];
            }
            float* ou = out + off_u8 + ((long long)((n * 224 + y) * 224 + xq)) * 3;
            *(float4*)(ou + 0) = make_float4(u[0], u[1], u[2],  u[3]);
            *(float4*)(ou + 4) = make_float4(u[4], u[5], u[6],  u[7]);
            *(float4*)(ou + 8) = make_float4(u[8], u[9], u[10], u[11]);
        }
    }
    __syncthreads();

    // ---- phase 2: owned t192 rows, flat parallel loop, 4 px per item ----
    float pa = 0.57142857f, pt = 32.f;
    float pdet = pa * pa;
    float pia  = pa / pdet;      // matches reference float arithmetic
    float pitx = -(pia * pt);

    int lo = sRange[0], hi = sRange[1];
    int cnt = hi - lo + 1;
    int items2 = (cnt > 0) ? cnt * 48 : 0;
    for (int it = tid; it < items2; it += 256) {
        int dy = it / 48;
        int y  = lo + dy;
        int xq = (it - dy * 48) * 4;

        float syf = pia * (float)y + pitx;
        float y0f = floorf(syf);
        int y0 = (int)y0f;
        float fy = syf - y0f;
        int y1 = y0 + 1;
        float vy0 = (y0 >= 0 && y0 < 224) ? 1.f : 0.f;
        float vy1 = (y1 >= 0 && y1 < 224) ? 1.f : 0.f;
        int y0c = min(max(y0, 0), 223);
        int y1c = min(max(y1, 0), 223);
        int ry0 = min(max(y0c - r0, 0), 8);
        int ry1 = min(max(y1c - r0, 0), 8);
        bool rowzero = (syf <= -1.f) | (syf >= 224.f);

        float o0[4], o1[4], o2[4];
#pragma unroll
        for (int j = 0; j < 4; j++) {
            int x = xq + j;
            float sxf = pia * (float)x + pitx;
            if (rowzero | (sxf <= -1.f) | (sxf >= 224.f)) {
                o0[j] = 0.f; o1[j] = 0.f; o2[j] = 0.f;
            } else {
                float x0f = floorf(sxf);
                int x0 = (int)x0f;
                float fx = sxf - x0f;
                int x1 = x0 + 1;
                float vx0 = (x0 >= 0 && x0 < 224) ? 1.f : 0.f;
                float vx1 = (x1 >= 0 && x1 < 224) ? 1.f : 0.f;
                float w00 = (1.f - fx) * (1.f - fy) * vx0 * vy0;
                float w10 = fx         * (1.f - fy) * vx1 * vy0;
                float w01 = (1.f - fx) * fy         * vx0 * vy1;
                float w11 = fx         * fy         * vx1 * vy1;
                int x0c = min(max(x0, 0), 223);
                int x1c = min(max(x1, 0), 223);
                o0[j] = sm[0][ry0][x0c]*w00 + sm[0][ry0][x1c]*w10
                      + sm[0][ry1][x0c]*w01 + sm[0][ry1][x1c]*w11;
                o1[j] = sm[1][ry0][x0c]*w00 + sm[1][ry0][x1c]*w10
                      + sm[1][ry1][x0c]*w01 + sm[1][ry1][x1c]*w11;
                o2[j] = sm[2][ry0][x0c]*w00 + sm[2][ry0][x1c]*w10
                      + sm[2][ry1][x0c]*w01 + sm[2][ry1][x1c]*w11;
            }
        }
        long long ob = off_t192 + ((long long)(n * 3) * 192 + y) * 192 + xq;
        *(float4*)(out + ob)               = make_float4(o0[0], o0[1], o0[2], o0[3]);
        *(float4*)(out + ob + 192*192)     = make_float4(o1[0], o1[1], o1[2], o1[3]);
        *(float4*)(out + ob + 2*192*192)   = make_float4(o2[0], o2[1], o2[2], o2[3]);
    }
}

// ---------------------------------------------------------------------------
extern "C" void kernel_launch(void* const* d_in, const int* in_sizes, int n_in,
                              void* d_out, int out_size)
{
    const float* xs  = (const float*)d_in[0];
    const float* img = (const float*)d_in[1];
    float* out = (float*)d_out;

    int N = in_sizes[0] / 10;   // (N,5,2)
    if (N > NMAX) N = NMAX;

    // output layout (float32): xs | IM_composed | imgs_u8 | t192 | M
    long long off_imc  = 10LL * N;
    long long off_u8   = off_imc + 6LL * N;
    long long off_t192 = off_u8 + 150528LL * N;   // 224*224*3
    long long off_M    = off_t192 + 110592LL * N; // 192*192*3

    prep_kernel<<<1026, 256>>>(img, xs, out, N, off_imc, off_M);
    fused_warp_kernel<<<28 * N, 256>>>(out, off_u8, off_t192);
}

// round 9
// speedup vs baseline: 3.8026x; 1.4278x over previous
#include <cuda_runtime.h>

#define NMAX 256

// Scratch (allocation-free rule: __device__ globals)
__device__ float4 g_img4[1024 * 1024];   // repacked source image (RGBA, pad=0)
__device__ float  g_IM[NMAX * 6];        // inverse affine per face
__device__ int2   g_rowrange[28];        // t192 rows owned by each 8-row tile

__constant__ float c_SRC[5][10] = {
    {103.284f,100.23f, 115.234f,99.98f, 71.48f,138.014f, 102.314f,178.1f,   114.05f,179.404f},
    {90.062f,100.236f, 131.136f,101.744f,79.354f,136.222f,90.354f,172.38f,  128.492f,173.516f},
    {79.46f,102.276f,  144.54f,102.276f, 112.0f,136.986f, 84.926f,174.02f,  139.074f,174.02f},
    {93.69f,101.744f,  134.764f,100.236f,145.474f,136.222f,96.334f,173.516f,134.472f,172.38f},
    {109.592f,99.98f,  121.542f,100.23f, 153.346f,138.014f,110.776f,179.404f,122.514f,178.1f}
};

// ---------------------------------------------------------------------------
// est: Umeyama over 5 templates, argmin, invert, compose. One thread/face.
// ---------------------------------------------------------------------------
__device__ void est_face(const float* __restrict__ xs, float* __restrict__ out,
                         int n, long long off_imc, long long off_M)
{
    float px[5], py[5];
#pragma unroll
    for (int i = 0; i < 5; i++) { px[i] = xs[n*10 + 2*i]; py[i] = xs[n*10 + 2*i + 1]; }

    float smx = 0.f, smy = 0.f;
#pragma unroll
    for (int i = 0; i < 5; i++) { smx += px[i]; smy += py[i]; }
    smx *= 0.2f; smy *= 0.2f;

    float sdx[5], sdy[5], var_sum = 0.f;
#pragma unroll
    for (int i = 0; i < 5; i++) {
        sdx[i] = px[i] - smx; sdy[i] = py[i] - smy;
        var_sum += sdx[i]*sdx[i] + sdy[i]*sdy[i];
    }
    var_sum *= 0.2f;

    float bestE = 3.4e38f;
    float bM[6] = {0,0,0,0,0,0};

#pragma unroll
    for (int k = 0; k < 5; k++) {
        const float* D = c_SRC[k];
        float dmx = 0.f, dmy = 0.f;
#pragma unroll
        for (int i = 0; i < 5; i++) { dmx += D[2*i]; dmy += D[2*i+1]; }
        dmx *= 0.2f; dmy *= 0.2f;

        float A00 = 0.f, A01 = 0.f, A10 = 0.f, A11 = 0.f;
#pragma unroll
        for (int i = 0; i < 5; i++) {
            float ddx = D[2*i]   - dmx;
            float ddy = D[2*i+1] - dmy;
            A00 += ddx * sdx[i]; A01 += ddx * sdy[i];
            A10 += ddy * sdx[i]; A11 += ddy * sdy[i];
        }
        A00 *= 0.2f; A01 *= 0.2f; A10 *= 0.2f; A11 *= 0.2f;

        float det = A00*A11 - A01*A10;
        float s   = (det > 0.f) ? 1.f : ((det < 0.f) ? -1.f : 0.f);

        float E = (A00 + A11) * 0.5f;
        float F = (A00 - A11) * 0.5f;
        float G = (A10 + A01) * 0.5f;
        float H = (A10 - A01) * 0.5f;
        float Q  = hypotf(E, H);
        float Rr = hypotf(F, G);
        float sxv = Q + Rr;
        float syv = Q - Rr;
        float a1 = atan2f(G, F);
        float a2 = atan2f(H, E);
        float beta  = (a2 - a1) * 0.5f;
        float gamma = (a2 + a1) * 0.5f;
        float cg = cosf(gamma), sg = sinf(gamma);
        float cb = cosf(beta),  sb = sinf(beta);
        float sgn = (syv < 0.f) ? -1.f : 1.f;
        float V00 = cb,        V01 = -sb;
        float V10 = sb * sgn,  V11 = cb * sgn;
        float R00 = cg * V00 - sg * s * V10;
        float R01 = cg * V01 - sg * s * V11;
        float R10 = sg * V00 + cg * s * V10;
        float R11 = sg * V01 + cg * s * V11;

        float scale = (sxv + fabsf(syv) * s) / var_sum;
        float tx = dmx - scale * (R00 * smx + R01 * smy);
        float ty = dmy - scale * (R10 * smx + R11 * smy);
        float M00 = scale * R00, M01 = scale * R01;
        float M10 = scale * R10, M11 = scale * R11;

        float e = 0.f;
#pragma unroll
        for (int i = 0; i < 5; i++) {
            float rx = M00*px[i] + M01*py[i] + tx - D[2*i];
            float ry = M10*px[i] + M11*py[i] + ty - D[2*i+1];
            e += sqrtf(rx*rx + ry*ry);
        }
        if (e < bestE) {
            bestE = e;
            bM[0] = M00; bM[1] = M01; bM[2] = tx;
            bM[3] = M10; bM[4] = M11; bM[5] = ty;
        }
    }

    float det = bM[0]*bM[4] - bM[1]*bM[3];
    float ia  =  bM[4] / det;
    float ib  = -bM[1] / det;
    float ic  = -bM[3] / det;
    float idd =  bM[0] / det;
    float itx = -(ia * bM[2] + ib  * bM[5]);
    float ity = -(ic * bM[2] + idd * bM[5]);

    g_IM[n*6+0] = ia;  g_IM[n*6+1] = ib;  g_IM[n*6+2] = itx;
    g_IM[n*6+3] = ic;  g_IM[n*6+4] = idd; g_IM[n*6+5] = ity;

    float pa = 0.57142857f, pt = 32.f;
    float pdet = pa * pa;
    float pia  = pa / pdet;
    float pitx = -(pia * pt);
    float C00 = ia  * pia,  C01 = ib  * pia;
    float C10 = ic  * pia,  C11 = idd * pia;
    float CT0 = ia * pitx + ib  * pitx + itx;
    float CT1 = ic * pitx + idd * pitx + ity;

#pragma unroll
    for (int j = 0; j < 10; j++) out[n*10 + j] = xs[n*10 + j];
    float* oc = out + off_imc + (long long)n * 6;
    oc[0] = C00; oc[1] = C01; oc[2] = CT0; oc[3] = C10; oc[4] = C11; oc[5] = CT1;
    float* om = out + off_M + (long long)n * 6;
    om[0] = bM[0]; om[1] = bM[1]; om[2] = bM[2]; om[3] = bM[3]; om[4] = bM[4]; om[5] = bM[5];
}

// ---------------------------------------------------------------------------
// Kernel A (prep): blocks [0,1024): img repack (4px/thread, float4 IO)
//                  block 1024: est for all faces
//                  block 1025: t192 tile row-ranges
// ---------------------------------------------------------------------------
__global__ __launch_bounds__(256) void prep_kernel(const float* __restrict__ img,
                                                   const float* __restrict__ xs,
                                                   float* __restrict__ out,
                                                   int N, long long off_imc, long long off_M)
{
    int blk = blockIdx.x;
    int tid = threadIdx.x;

    if (blk < 1024) {
        int j = blk * 256 + tid;            // 4-pixel group id, j < 262144
        const float4* im4 = (const float4*)img;
        float4 a = im4[3*j+0];
        float4 b = im4[3*j+1];
        float4 c = im4[3*j+2];
        g_img4[4*j+0] = make_float4(a.x, a.y, a.z, 0.f);
        g_img4[4*j+1] = make_float4(a.w, b.x, b.y, 0.f);
        g_img4[4*j+2] = make_float4(b.z, b.w, c.x, 0.f);
        g_img4[4*j+3] = make_float4(c.y, c.z, c.w, 0.f);
    } else if (blk == 1024) {
        if (tid < N) est_face(xs, out, tid, off_imc, off_M);
    } else {
        __shared__ int s_lo[28], s_hi[28];
        if (tid < 28) { s_lo[tid] = 192; s_hi[tid] = -1; }
        __syncthreads();
        if (tid < 192) {
            float pa = 0.57142857f, pt = 32.f;
            float pdet = pa * pa;
            float pia  = pa / pdet;
            float pitx = -(pia * pt);
            float syf = pia * (float)tid + pitx;
            int y0 = (int)floorf(syf);
            int t = (y0 < 0) ? 0 : ((y0 >= 224) ? 27 : (y0 >> 3));
            atomicMin(&s_lo[t], tid);
            atomicMax(&s_hi[t], tid);
        }
        __syncthreads();
        if (tid < 28) g_rowrange[tid] = make_int2(s_lo[tid], s_hi[tid]);
    }
}

// ---------------------------------------------------------------------------
// Kernel B (fused): per (face, 8-row tile):
//   phase 1: bilinear-warp img -> 9-row t224 tile in smem (+u8 output, 8 rows)
//            with all-out-of-bounds skip (zero taps -> zero loads)
//   phase 2: 1.75x-zoom bilinear tile -> owned t192 rows
// ---------------------------------------------------------------------------
__global__ __launch_bounds__(256) void fused_warp_kernel(float* __restrict__ out,
                                                         long long off_u8,
                                                         long long off_t192)
{
    __shared__ float sm[3][9][224];   // 24192 B tile (halo row included)
    __shared__ float sIM[6];
    __shared__ int   sRange[2];

    int blk  = blockIdx.x;
    int tile = blk % 28;
    int n    = blk / 28;
    int r0   = tile * 8;
    int tid  = threadIdx.x;

    if (tid < 6) sIM[tid] = g_IM[n*6 + tid];
    if (tid == 6) { int2 rr = g_rowrange[tile]; sRange[0] = rr.x; sRange[1] = rr.y; }
    __syncthreads();
    float i0 = sIM[0], i1 = sIM[1], i2 = sIM[2];
    float i3 = sIM[3], i4 = sIM[4], i5 = sIM[5];

    // ---- phase 1: fill t224 tile, 4 px per thread-item ----
    int rows   = (r0 + 8 < 224) ? 9 : 8;
    int items4 = rows * 56;                      // 56 groups of 4 px per row
    for (int it = tid; it < items4; it += 256) {
        int ry = it / 56;
        int xq = (it - ry * 56) * 4;
        int y  = r0 + ry;
        float gy = (float)y;

        float sxv[4], syv[4];
#pragma unroll
        for (int j = 0; j < 4; j++) {
            float gx = (float)(xq + j);
            sxv[j] = i0 * gx + i1 * gy + i2;
            syv[j] = i3 * gx + i4 * gy + i5;
        }

        // Group-level OOB skip: affine is linear along the segment, so the
        // endpoints bound sx,sy for all 4 px. All 16 taps have weight 0 iff
        // the whole segment lies in sx<=-1 | sx>=1024 | sy<=-1 | sy>=1024.
        bool group_zero =
            (sxv[0] <= -1.f   && sxv[3] <= -1.f)   ||
            (sxv[0] >= 1024.f && sxv[3] >= 1024.f) ||
            (syv[0] <= -1.f   && syv[3] <= -1.f)   ||
            (syv[0] >= 1024.f && syv[3] >= 1024.f);

        float rr[4], gg[4], bb[4];
        if (group_zero) {
#pragma unroll
            for (int j = 0; j < 4; j++) { rr[j] = 0.f; gg[j] = 0.f; bb[j] = 0.f; }
        } else {
            bool interior = (sxv[0] >= 0.f) & (sxv[0] < 1023.f) &
                            (sxv[3] >= 0.f) & (sxv[3] < 1023.f) &
                            (syv[0] >= 0.f) & (syv[0] < 1023.f) &
                            (syv[3] >= 0.f) & (syv[3] < 1023.f);
            if (interior) {
#pragma unroll
                for (int j = 0; j < 4; j++) {
                    float x0f = floorf(sxv[j]), y0f = floorf(syv[j]);
                    float fx = sxv[j] - x0f,    fy = syv[j] - y0f;
                    int x0 = (int)x0f, y0 = (int)y0f;
                    float w00 = (1.f - fx) * (1.f - fy);
                    float w10 = fx         * (1.f - fy);
                    float w01 = (1.f - fx) * fy;
                    float w11 = fx         * fy;
                    int base0 = y0 * 1024 + x0;
                    float4 v00 = g_img4[base0];
                    float4 v10 = g_img4[base0 + 1];
                    float4 v01 = g_img4[base0 + 1024];
                    float4 v11 = g_img4[base0 + 1025];
                    rr[j] = v00.x*w00 + v10.x*w10 + v01.x*w01 + v11.x*w11;
                    gg[j] = v00.y*w00 + v10.y*w10 + v01.y*w01 + v11.y*w11;
                    bb[j] = v00.z*w00 + v10.z*w10 + v01.z*w01 + v11.z*w11;
                }
            } else {
#pragma unroll
                for (int j = 0; j < 4; j++) {
                    // per-pixel OOB skip
                    if (sxv[j] <= -1.f || sxv[j] >= 1024.f ||
                        syv[j] <= -1.f || syv[j] >= 1024.f) {
                        rr[j] = 0.f; gg[j] = 0.f; bb[j] = 0.f;
                        continue;
                    }
                    float x0f = floorf(sxv[j]), y0f = floorf(syv[j]);
                    float fx = sxv[j] - x0f,    fy = syv[j] - y0f;
                    int x0 = (int)x0f, y0 = (int)y0f;
                    int x1 = x0 + 1,   y1 = y0 + 1;
                    const int W = 1024, H = 1024;
                    float vx0 = (x0 >= 0 && x0 < W) ? 1.f : 0.f;
                    float vx1 = (x1 >= 0 && x1 < W) ? 1.f : 0.f;
                    float vy0 = (y0 >= 0 && y0 < H) ? 1.f : 0.f;
                    float vy1 = (y1 >= 0 && y1 < H) ? 1.f : 0.f;
                    float w00 = (1.f - fx) * (1.f - fy) * vx0 * vy0;
                    float w10 = fx         * (1.f - fy) * vx1 * vy0;
                    float w01 = (1.f - fx) * fy         * vx0 * vy1;
                    float w11 = fx         * fy         * vx1 * vy1;
                    int x0c = min(max(x0, 0), W-1), x1c = min(max(x1, 0), W-1);
                    int y0c = min(max(y0, 0), H-1), y1c = min(max(y1, 0), H-1);
                    float4 v00 = g_img4[y0c * W + x0c];
                    float4 v10 = g_img4[y0c * W + x1c];
                    float4 v01 = g_img4[y1c * W + x0c];
                    float4 v11 = g_img4[y1c * W + x1c];
                    rr[j] = v00.x*w00 + v10.x*w10 + v01.x*w01 + v11.x*w11;
                    gg[j] = v00.y*w00 + v10.y*w10 + v01.y*w01 + v11.y*w11;
                    bb[j] = v00.z*w00 + v10.z*w10 + v01.z*w01 + v11.z*w11;
                }
            }
        }

        *(float4*)&sm[0][ry][xq] = make_float4(rr[0], rr[1], rr[2], rr[3]);
        *(float4*)&sm[1][ry][xq] = make_float4(gg[0], gg[1], gg[2], gg[3]);
        *(float4*)&sm[2][ry][xq] = make_float4(bb[0], bb[1], bb[2], bb[3]);

        if (ry < 8) {
            float u[12];
#pragma unroll
            for (int j = 0; j < 4; j++) {
                u[3*j+0] = (float)(unsigned char)rr[j];
                u[3*j+1] = (float)(unsigned char)gg[j];
                u[3*j+2] = (float)(unsigned char)bb[j];
            }
            float* ou = out + off_u8 + ((long long)((n * 224 + y) * 224 + xq)) * 3;
            *(float4*)(ou + 0) = make_float4(u[0], u[1], u[2],  u[3]);
            *(float4*)(ou + 4) = make_float4(u[4], u[5], u[6],  u[7]);
            *(float4*)(ou + 8) = make_float4(u[8], u[9], u[10], u[11]);
        }
    }
    __syncthreads();

    // ---- phase 2: owned t192 rows, flat parallel loop, 4 px per item ----
    float pa = 0.57142857f, pt = 32.f;
    float pdet = pa * pa;
    float pia  = pa / pdet;      // matches reference float arithmetic
    float pitx = -(pia * pt);

    int lo = sRange[0], hi = sRange[1];
    int cnt = hi - lo + 1;
    int items2 = (cnt > 0) ? cnt * 48 : 0;
    for (int it = tid; it < items2; it += 256) {
        int dy = it / 48;
        int y  = lo + dy;
        int xq = (it - dy * 48) * 4;

        float syf = pia * (float)y + pitx;
        float y0f = floorf(syf);
        int y0 = (int)y0f;
        float fy = syf - y0f;
        int y1 = y0 + 1;
        float vy0 = (y0 >= 0 && y0 < 224) ? 1.f : 0.f;
        float vy1 = (y1 >= 0 && y1 < 224) ? 1.f : 0.f;
        int y0c = min(max(y0, 0), 223);
        int y1c = min(max(y1, 0), 223);
        int ry0 = min(max(y0c - r0, 0), 8);
        int ry1 = min(max(y1c - r0, 0), 8);
        bool rowzero = (syf <= -1.f) | (syf >= 224.f);

        float o0[4], o1[4], o2[4];
#pragma unroll
        for (int j = 0; j < 4; j++) {
            int x = xq + j;
            float sxf = pia * (float)x + pitx;
            if (rowzero | (sxf <= -1.f) | (sxf >= 224.f)) {
                o0[j] = 0.f; o1[j] = 0.f; o2[j] = 0.f;
            } else {
                float x0f = floorf(sxf);
                int x0 = (int)x0f;
                float fx = sxf - x0f;
                int x1 = x0 + 1;
                float vx0 = (x0 >= 0 && x0 < 224) ? 1.f : 0.f;
                float vx1 = (x1 >= 0 && x1 < 224) ? 1.f : 0.f;
                float w00 = (1.f - fx) * (1.f - fy) * vx0 * vy0;
                float w10 = fx         * (1.f - fy) * vx1 * vy0;
                float w01 = (1.f - fx) * fy         * vx0 * vy1;
                float w11 = fx         * fy         * vx1 * vy1;
                int x0c = min(max(x0, 0), 223);
                int x1c = min(max(x1, 0), 223);
                o0[j] = sm[0][ry0][x0c]*w00 + sm[0][ry0][x1c]*w10
                      + sm[0][ry1][x0c]*w01 + sm[0][ry1][x1c]*w11;
                o1[j] = sm[1][ry0][x0c]*w00 + sm[1][ry0][x1c]*w10
                      + sm[1][ry1][x0c]*w01 + sm[1][ry1][x1c]*w11;
                o2[j] = sm[2][ry0][x0c]*w00 + sm[2][ry0][x1c]*w10
                      + sm[2][ry1][x0c]*w01 + sm[2][ry1][x1c]*w11;
            }
        }
        long long ob = off_t192 + ((long long)(n * 3) * 192 + y) * 192 + xq;
        *(float4*)(out + ob)               = make_float4(o0[0], o0[1], o0[2], o0[3]);
        *(float4*)(out + ob + 192*192)     = make_float4(o1[0], o1[1], o1[2], o1[3]);
        *(float4*)(out + ob + 2*192*192)   = make_float4(o2[0], o2[1], o2[2], o2[3]);
    }
}

// ---------------------------------------------------------------------------
extern "C" void kernel_launch(void* const* d_in, const int* in_sizes, int n_in,
                              void* d_out, int out_size)
{
    const float* xs  = (const float*)d_in[0];
    const float* img = (const float*)d_in[1];
    float* out = (float*)d_out;

    int N = in_sizes[0] / 10;   // (N,5,2)
    if (N > NMAX) N = NMAX;

    // output layout (float32): xs | IM_composed | imgs_u8 | t192 | M
    long long off_imc  = 10LL * N;
    long long off_u8   = off_imc + 6LL * N;
    long long off_t192 = off_u8 + 150528LL * N;   // 224*224*3
    long long off_M    = off_t192 + 110592LL * N; // 192*192*3

    prep_kernel<<<1026, 256>>>(img, xs, out, N, off_imc, off_M);
    fused_warp_kernel<<<28 * N, 256>>>(out, off_u8, off_t192);
}